// round 13
// baseline (speedup 1.0000x reference)
#include <cuda_runtime.h>
#include <cuda_fp16.h>
#include <cstdint>

#define Bv 4
#define Sv 2048
#define Hv 768
#define NHv 12
#define DHv 64
#define WHv 128

typedef __half f16;
typedef unsigned int u32;

// ---------------- scratch (static device globals) ---------------------------
__device__ f16 g_hsh[(size_t)Bv*Sv*Hv];
__device__ f16 g_Wth[(size_t)4*Hv*Hv];      // W^T, rows: [q|k|v|o]
__device__ f16 g_Qh[(size_t)Bv*NHv*Sv*DHv];
__device__ f16 g_Kh[(size_t)Bv*NHv*Sv*DHv];
__device__ f16 g_Vth[(size_t)Bv*NHv*DHv*Sv];   // [z][dh][s]
__device__ f16 g_Eh[(size_t)Bv*NHv*Sv*Sv];     // unnormalized exp, fp16
__device__ f16 g_ctxh[(size_t)Bv*Sv*Hv];
__device__ float g_preln[(size_t)Bv*Sv*Hv];
__device__ float g_gates[Bv*NHv*Sv];
__device__ float g_rowL[Bv*NHv*Sv];

// ---------------- asm helpers ------------------------------------------------
__device__ __forceinline__ void mma16816(float& c0, float& c1, float& c2, float& c3,
                                         const u32 a[4], const u32 b[2]){
    asm volatile("mma.sync.aligned.m16n8k16.row.col.f32.f16.f16.f32 "
        "{%0,%1,%2,%3}, {%4,%5,%6,%7}, {%8,%9}, {%0,%1,%2,%3};"
        : "+f"(c0), "+f"(c1), "+f"(c2), "+f"(c3)
        : "r"(a[0]), "r"(a[1]), "r"(a[2]), "r"(a[3]), "r"(b[0]), "r"(b[1]));
}
// .cg: bypass L1 (all tiles are read-once; keeps L1 free for LDSM/STG traffic)
__device__ __forceinline__ void cpa16(void* s, const void* g){
    asm volatile("cp.async.cg.shared.global [%0], [%1], 16;\n"
        :: "r"((u32)__cvta_generic_to_shared(s)), "l"(g));
}
__device__ __forceinline__ void ldm_x4(u32& r0,u32& r1,u32& r2,u32& r3, const void* p){
    asm volatile("ldmatrix.sync.aligned.m8n8.x4.shared.b16 {%0,%1,%2,%3}, [%4];"
        : "=r"(r0),"=r"(r1),"=r"(r2),"=r"(r3)
        : "r"((u32)__cvta_generic_to_shared(p)));
}
#define CP_COMMIT() asm volatile("cp.async.commit_group;\n")
#define CP_WAIT0()  asm volatile("cp.async.wait_group 0;\n")
#define CP_WAIT1()  asm volatile("cp.async.wait_group 1;\n")

// ---------------- prep kernels -----------------------------------------------
__global__ __launch_bounds__(256) void cvt_kernel(const float* __restrict__ x,
    f16* __restrict__ h, int n4)
{
    int i = blockIdx.x*256 + threadIdx.x;
    if (i >= n4) return;
    float4 v = ((const float4*)x)[i];
    ((__half2*)h)[i*2  ] = __floats2half2_rn(v.x, v.y);
    ((__half2*)h)[i*2+1] = __floats2half2_rn(v.z, v.w);
}

__global__ __launch_bounds__(256) void wsplit_kernel(
    const float* __restrict__ w0, const float* __restrict__ w1,
    const float* __restrict__ w2, const float* __restrict__ w3)
{
    __shared__ float t[32][33];
    const float* W = blockIdx.z==0 ? w0 : blockIdx.z==1 ? w1 : blockIdx.z==2 ? w2 : w3;
    f16* oh = g_Wth + (size_t)blockIdx.z*Hv*Hv;
    int k0 = blockIdx.y*32, n0 = blockIdx.x*32;
    int tx = threadIdx.x & 31, ty = threadIdx.x >> 5;   // (32,8)
    #pragma unroll
    for (int r=0;r<32;r+=8) t[ty+r][tx] = W[(size_t)(k0+ty+r)*Hv + n0+tx];
    __syncthreads();
    #pragma unroll
    for (int r=0;r<32;r+=8){
        float v = t[tx][ty+r];                 // = W[k0+tx][n0+ty+r]
        oh[(size_t)(n0+ty+r)*Hv + k0+tx] = __float2half_rn(v);
    }
}

// ---------------- 1-term fp16 tensor-core GEMM (BK=64, ldmatrix, cp.async) ---
// C[M,N] = A[M,K] @ B^T[N,K]
// MODE 3: scores -> E = exp(gate*qk/8 + mask) fp16 + rowL atomics  (K=64: 1 iter)
// MODE 4: Wo proj -> preln fp32, +bias +resid
// MODE 5: fused QKV (N=3H): Q,K -> fp16 [b,nh,s,dh]; V -> fp16 [b,nh,dh,s]
template<int MODE>
__global__ __launch_bounds__(256,2) void mmagemm(
    const f16* __restrict__ Ah, int lda, size_t sA,
    const f16* __restrict__ Bh, int ldb, size_t sB,
    const float* __restrict__ bias0, const float* __restrict__ bias1,
    const float* __restrict__ bias2,
    const float* __restrict__ e1,   // gates (M3) / resid (M4)
    const float* __restrict__ e2,   // attention_mask (M3)
    f16* __restrict__ O0, f16* __restrict__ O1, f16* __restrict__ O2,
    float* __restrict__ Of, float* __restrict__ Ex,
    int K)
{
    constexpr int LDSK = 72;                   // 64 + 8 pad; 144B stride, LDSM-conflict-free
    constexpr int BUF  = 128*LDSK;
    extern __shared__ f16 smem[];
    f16* sAh = smem;
    f16* sBh = sAh + 2*BUF;

    const int tid  = threadIdx.x, lane = tid & 31, warp = tid >> 5;
    const int grp  = lane >> 2,   tig  = lane & 3;
    const int z    = blockIdx.z;
    const int row0 = blockIdx.y*128, col0 = blockIdx.x*128;
    const f16* A_h = Ah + (size_t)z*sA;
    const f16* B_h = Bh + (size_t)z*sB;
    const int warpM = (warp>>2)*64, warpN = (warp&3)*32;
    const int aRow  = lane & 15,        aCol8 = (lane >> 4) * 8;
    const int bRow  = (lane & 7) + ((lane >> 4) << 3);
    const int bCol8 = ((lane >> 3) & 1) * 8;

    float c[4][4][4];
    #pragma unroll
    for (int i=0;i<4;i++)
        #pragma unroll
        for (int j=0;j<4;j++)
            #pragma unroll
            for (int r=0;r<4;r++) c[i][j][r]=0.f;

    const int lr = tid>>1, lcb = (tid&1)*32;   // row, f16-col base (4 chunks of 8)
    auto load_tile = [&](int kt, int st){
        const int k0 = kt*64;
        f16* dA = sAh + st*BUF; f16* dB = sBh + st*BUF;
        #pragma unroll
        for (int cc=0;cc<4;cc++){
            cpa16(&dA[lr*LDSK + lcb + cc*8], &A_h[(size_t)(row0+lr)*lda + k0 + lcb + cc*8]);
            cpa16(&dB[lr*LDSK + lcb + cc*8], &B_h[(size_t)(col0+lr)*ldb + k0 + lcb + cc*8]);
        }
    };

    const int KT = K/64;
    load_tile(0, 0); CP_COMMIT();

    for (int kt=0; kt<KT; kt++){
        const int st = kt & 1;
        __syncthreads();                       // prev compute on st^1 done (WAR)
        if (kt+1 < KT){ load_tile(kt+1, st^1); CP_COMMIT(); CP_WAIT1(); }
        else          { CP_WAIT0(); }
        __syncthreads();                       // tile st visible to all
        const f16* pAh = sAh + st*BUF;
        const f16* pBh = sBh + st*BUF;
        #pragma unroll
        for (int ks=0;ks<64;ks+=16){
            u32 a[4][4], b_h[4][2];
            #pragma unroll
            for (int jj=0; jj<4; jj+=2)
                ldm_x4(b_h[jj][0], b_h[jj][1], b_h[jj+1][0], b_h[jj+1][1],
                       &pBh[(warpN + jj*8 + bRow)*LDSK + ks + bCol8]);
            #pragma unroll
            for (int i=0;i<4;i++)
                ldm_x4(a[i][0],a[i][1],a[i][2],a[i][3],
                       &pAh[(warpM + i*16 + aRow)*LDSK + ks + aCol8]);
            #pragma unroll
            for (int i=0;i<4;i++)
                #pragma unroll
                for (int j=0;j<4;j++)
                    mma16816(c[i][j][0],c[i][j][1],c[i][j][2],c[i][j][3], a[i], b_h[j]);
        }
    }

    if (MODE==3){
        // E = exp(...) stored fp16 + rowL atomics (fp32 partial sums)
        float* rowLp = Ex + (size_t)z*Sv;
        const float* mk = e2 + (size_t)(z/NHv)*Sv;
        f16* Ez = O0 + (size_t)z*Sv*Sv;
        #pragma unroll
        for (int i=0;i<4;i++){
            #pragma unroll
            for (int half=0; half<2; half++){
                int r = row0 + warpM + i*16 + grp + half*8;
                float g = e1[(size_t)z*Sv + r]*0.125f;
                float rs = 0.f;
                #pragma unroll
                for (int j=0;j<4;j++){
                    int cn = col0 + warpN + j*8 + tig*2;
                    float s0 = c[i][j][half*2  ]*g + (1.f-mk[cn  ])*-10000.f;
                    float s1 = c[i][j][half*2+1]*g + (1.f-mk[cn+1])*-10000.f;
                    float e0 = __expf(s0), e1v = __expf(s1);
                    rs += e0 + e1v;
                    *(__half2*)(Ez + (size_t)r*Sv + cn) = __floats2half2_rn(e0, e1v);
                }
                rs += __shfl_xor_sync(0xffffffffu, rs, 1);
                rs += __shfl_xor_sync(0xffffffffu, rs, 2);
                if (tig==0) atomicAdd(&rowLp[r], rs);
            }
        }
    } else if (MODE==5){
        const int w = col0/Hv;                 // 0=Q 1=K 2=V
        const float* bias = w==0?bias0 : w==1?bias1 : bias2;
        #pragma unroll
        for (int i=0;i<4;i++){
            #pragma unroll
            for (int j=0;j<4;j++){
                int cn  = col0 + warpN + j*8 + tig*2;
                int cl  = cn - w*Hv;
                int nh  = cl>>6, dh = cl&63;
                #pragma unroll
                for (int half=0; half<2; half++){
                    int r = row0 + warpM + i*16 + grp + half*8;
                    float x0 = c[i][j][half*2  ] + bias[cl  ];
                    float x1 = c[i][j][half*2+1] + bias[cl+1];
                    int b=r/Sv, s=r-b*Sv;
                    if (w<2){
                        size_t idx = (((size_t)(b*NHv+nh)*Sv+s)<<6)+dh;
                        f16* PO = w==0 ? O0 : O1;
                        *(__half2*)(PO+idx) = __floats2half2_rn(x0,x1);
                    } else {
                        size_t i0 = ((size_t)(b*NHv+nh)*DHv+dh)*Sv + s;
                        O2[i0]    = __float2half_rn(x0);
                        O2[i0+Sv] = __float2half_rn(x1);
                    }
                }
            }
        }
    } else {   // MODE 4: Of = preln, e1 = residual (hs)
        #pragma unroll
        for (int i=0;i<4;i++){
            #pragma unroll
            for (int j=0;j<4;j++){
                int cn = col0 + warpN + j*8 + tig*2;
                #pragma unroll
                for (int half=0; half<2; half++){
                    int r = row0 + warpM + i*16 + grp + half*8;
                    size_t idx = (size_t)r*Hv + cn;
                    float2 o;
                    o.x = c[i][j][half*2  ] + bias0[cn  ] + e1[idx  ];
                    o.y = c[i][j][half*2+1] + bias0[cn+1] + e1[idx+1];
                    *(float2*)(Of+idx) = o;
                }
            }
        }
    }
}

// ---------------- PV: probs = e*inv (fp32 out) + ctx = (E@V)*inv -------------
__global__ __launch_bounds__(256,2) void pv_kernel(
    float* __restrict__ probs,
    const f16* __restrict__ Eh, const f16* __restrict__ Vth,
    const float* __restrict__ rowL,
    f16* __restrict__ ctxh)
{
    constexpr int LDSK = 72;
    constexpr int EST  = 128*LDSK;             // f16 elems per E stage
    constexpr int VST  = 64*LDSK;              // f16 elems per V stage
    extern __shared__ char pvs[];
    f16* sE  = (f16*)pvs;                                   // 2 st * 18432B
    f16* sV  = (f16*)(pvs + 36864);                         // 2 st * 9216B
    float* sI = (float*)(pvs + 55296);                      // 512B

    const int tid = threadIdx.x, lane = tid & 31, warp = tid >> 5;
    const int grp = lane >> 2, tig = lane & 3;
    const int z = blockIdx.y, q0 = blockIdx.x*128;
    const int aRow  = lane & 15,        aCol8 = (lane >> 4) * 8;
    const int bRow  = (lane & 7) + ((lane >> 4) << 3);
    const int bCol8 = ((lane >> 3) & 1) * 8;

    if (tid < 128) sI[tid] = 1.f / rowL[(size_t)z*Sv + q0 + tid];

    const int warpM = (warp>>1)*32, warpN = (warp&1)*32;
    float c[2][4][4];
    #pragma unroll
    for (int i=0;i<2;i++)
        #pragma unroll
        for (int j=0;j<4;j++)
            #pragma unroll
            for (int r=0;r<4;r++) c[i][j][r]=0.f;

    float* Pz = probs + (size_t)z*Sv*Sv;
    const f16* Ez = Eh + (size_t)z*Sv*Sv;
    const f16* V_ = Vth + (size_t)z*DHv*Sv;

    const int er = tid>>1, ecb = (tid&1)*32;   // E: row, f16-col base
    const int vr = tid>>2, vcb = (tid&3)*16;   // V: row, f16-col base (2 chunks)
    auto prefetch = [&](int kt, int st){
        const int k0 = kt*64;
        #pragma unroll
        for (int cc=0;cc<4;cc++)
            cpa16(&sE[st*EST + er*LDSK + ecb + cc*8], &Ez[(size_t)(q0+er)*Sv + k0 + ecb + cc*8]);
        #pragma unroll
        for (int cc=0;cc<2;cc++)
            cpa16(&sV[st*VST + vr*LDSK + vcb + cc*8], &V_[(size_t)vr*Sv + k0 + vcb + cc*8]);
    };

    prefetch(0, 0); CP_COMMIT();

    for (int kt=0; kt<Sv/64; kt++){
        const int st = kt & 1;
        __syncthreads();                       // prev reads of st^1 done (WAR)
        if (kt+1 < Sv/64){ prefetch(kt+1, st^1); CP_COMMIT(); CP_WAIT1(); }
        else             { CP_WAIT0(); }
        __syncthreads();                       // stage st arrived for all
        {   // probs = e*inv (fp32) straight from smem
            const int k0 = kt*64;
            const float inv = sI[er];
            const f16* pe = sE + st*EST + er*LDSK + ecb;
            float* po = &Pz[(size_t)(q0+er)*Sv + k0 + ecb];
            #pragma unroll
            for (int c4=0;c4<8;c4++){
                __half2 e01 = *(__half2*)(pe + c4*4);
                __half2 e23 = *(__half2*)(pe + c4*4 + 2);
                float4 o;
                o.x = __low2float(e01)*inv;  o.y = __high2float(e01)*inv;
                o.z = __low2float(e23)*inv;  o.w = __high2float(e23)*inv;
                *(float4*)(po + c4*4) = o;
            }
        }
        const f16* pE = sE + st*EST;
        const f16* pV = sV + st*VST;
        #pragma unroll
        for (int ks=0;ks<64;ks+=16){
            u32 a[2][4], b_h[4][2];
            #pragma unroll
            for (int jj=0; jj<4; jj+=2)
                ldm_x4(b_h[jj][0], b_h[jj][1], b_h[jj+1][0], b_h[jj+1][1],
                       &pV[(warpN + jj*8 + bRow)*LDSK + ks + bCol8]);
            #pragma unroll
            for (int i=0;i<2;i++)
                ldm_x4(a[i][0],a[i][1],a[i][2],a[i][3],
                       &pE[(warpM + i*16 + aRow)*LDSK + ks + aCol8]);
            #pragma unroll
            for (int i=0;i<2;i++)
                #pragma unroll
                for (int j=0;j<4;j++)
                    mma16816(c[i][j][0],c[i][j][1],c[i][j][2],c[i][j][3], a[i], b_h[j]);
        }
    }

    const int b = z/NHv, nh = z%NHv;
    #pragma unroll
    for (int i=0;i<2;i++){
        #pragma unroll
        for (int j=0;j<4;j++){
            int dh = warpN + j*8 + tig*2;
            #pragma unroll
            for (int half=0; half<2; half++){
                int sl = warpM + i*16 + grp + half*8;
                int s  = q0 + sl;
                float inv = sI[sl];
                float x0 = c[i][j][half*2]*inv, x1 = c[i][j][half*2+1]*inv;
                size_t idx = ((size_t)b*Sv + s)*Hv + nh*DHv + dh;
                *(__half2*)(ctxh+idx) = __floats2half2_rn(x0,x1);
            }
        }
    }
}

// ---------------- helpers ----------------------------------------------------
__device__ __forceinline__ float blockReduceSum(float v, float* red){
    #pragma unroll
    for (int o=16;o;o>>=1) v += __shfl_xor_sync(0xffffffffu, v, o);
    const int lane = threadIdx.x & 31, wid = threadIdx.x >> 5;
    const int nw = blockDim.x >> 5;
    __syncthreads();
    if (lane==0) red[wid]=v;
    __syncthreads();
    if (threadIdx.x==0){
        float s=0.f;
        for (int i=0;i<nw;i++) s+=red[i];
        red[32]=s;
    }
    __syncthreads();
    return red[32];
}

// ---------------- wormhole gate ----------------------------------------------
__global__ __launch_bounds__(128) void gate_kernel(
    const float* __restrict__ hs, const float* __restrict__ Wg1, const float* __restrict__ bg1,
    const float* __restrict__ glnw, const float* __restrict__ glnb,
    const float* __restrict__ Wg2, const float* __restrict__ bg2,
    float* __restrict__ gates)
{
    const int ROWS=8;
    __shared__ float hs_s[ROWS*Hv];
    __shared__ float g_s[ROWS][WHv+4];
    __shared__ float red[40];
    const int tid = threadIdx.x;
    const size_t rowbase = (size_t)blockIdx.x*ROWS;

    for (int i=tid;i<ROWS*Hv;i+=128) hs_s[i] = hs[rowbase*Hv + i];
    __syncthreads();

    float acc[ROWS];
    #pragma unroll
    for (int r=0;r<ROWS;r++) acc[r]=bg1[tid];
    for (int h=0;h<Hv;h++){
        float wv = Wg1[h*WHv + tid];
        #pragma unroll
        for (int r=0;r<ROWS;r++) acc[r] = fmaf(hs_s[r*Hv+h], wv, acc[r]);
    }
    float lw = glnw[tid], lb = glnb[tid];
    #pragma unroll
    for (int r=0;r<ROWS;r++){
        float mu  = blockReduceSum(acc[r], red) * (1.f/WHv);
        float d   = acc[r]-mu;
        float var = blockReduceSum(d*d, red) * (1.f/WHv);
        float gv  = d*rsqrtf(var+1e-12f)*lw + lb;
        g_s[r][tid] = fmaxf(gv, 0.f);
    }
    __syncthreads();
    if (tid < ROWS*NHv){
        int r = tid/NHv, o = tid%NHv;
        float s = bg2[o];
        for (int c=0;c<WHv;c++) s = fmaf(g_s[r][c], Wg2[c*NHv+o], s);
        float gate = 1.f/(1.f+__expf(-s));
        size_t row = rowbase + r;
        int b = (int)(row/Sv), sq = (int)(row%Sv);
        gates[((size_t)(b*NHv+o))*Sv + sq] = gate;
    }
}

// ---------------- final residual LayerNorm -----------------------------------
__global__ __launch_bounds__(256) void ln_kernel(const float* __restrict__ x,
    const float* __restrict__ w, const float* __restrict__ b, float* __restrict__ out)
{
    __shared__ float xs[Hv];
    __shared__ float red[40];
    const size_t row = blockIdx.x;
    const float* xr = x + row*Hv;
    float partial = 0.f;
    for (int i=threadIdx.x;i<Hv;i+=256){ float v=xr[i]; xs[i]=v; partial+=v; }
    float mu = blockReduceSum(partial, red)*(1.f/Hv);
    float p2=0.f;
    for (int i=threadIdx.x;i<Hv;i+=256){ float d=xs[i]-mu; p2+=d*d; }
    float var = blockReduceSum(p2, red)*(1.f/Hv);
    float rs = rsqrtf(var+1e-12f);
    float* o = out + row*Hv;
    for (int i=threadIdx.x;i<Hv;i+=256) o[i] = (xs[i]-mu)*rs*w[i] + b[i];
}

// ---------------- launcher ----------------------------------------------------
extern "C" void kernel_launch(void* const* d_in, const int* in_sizes, int n_in,
                              void* d_out, int out_size)
{
    const float* hs  =(const float*)d_in[0];
    const float* am  =(const float*)d_in[1];
    const float* Wq  =(const float*)d_in[2];
    const float* bq  =(const float*)d_in[3];
    const float* Wk  =(const float*)d_in[4];
    const float* bk  =(const float*)d_in[5];
    const float* Wv  =(const float*)d_in[6];
    const float* bvb =(const float*)d_in[7];
    const float* Wg1 =(const float*)d_in[8];
    const float* bg1 =(const float*)d_in[9];
    const float* glnw=(const float*)d_in[10];
    const float* glnb=(const float*)d_in[11];
    const float* Wg2 =(const float*)d_in[12];
    const float* bg2 =(const float*)d_in[13];
    const float* Wo  =(const float*)d_in[14];
    const float* bo  =(const float*)d_in[15];
    const float* lnw =(const float*)d_in[16];
    const float* lnb =(const float*)d_in[17];

    float* out   = (float*)d_out;
    float* probs = out + (size_t)Bv*Sv*Hv;   // tuple order: (out, probs)

    f16 *hsh,*Wth,*Qh,*Kh,*Vth,*Eh,*ctxh;
    float *preln,*gates,*rowL;
    cudaGetSymbolAddress((void**)&hsh,  g_hsh);
    cudaGetSymbolAddress((void**)&Wth,  g_Wth);
    cudaGetSymbolAddress((void**)&Qh,   g_Qh);
    cudaGetSymbolAddress((void**)&Kh,   g_Kh);
    cudaGetSymbolAddress((void**)&Vth,  g_Vth);
    cudaGetSymbolAddress((void**)&Eh,   g_Eh);
    cudaGetSymbolAddress((void**)&ctxh, g_ctxh);
    cudaGetSymbolAddress((void**)&preln,g_preln);
    cudaGetSymbolAddress((void**)&gates,g_gates);
    cudaGetSymbolAddress((void**)&rowL, g_rowL);

    const int M = Bv*Sv;
    const int SMEM_GEMM = 4*128*72*(int)sizeof(f16);     // 73728 B
    const int SMEM_PV   = 55808;

    cudaFuncSetAttribute(mmagemm<3>, cudaFuncAttributeMaxDynamicSharedMemorySize, SMEM_GEMM);
    cudaFuncSetAttribute(mmagemm<4>, cudaFuncAttributeMaxDynamicSharedMemorySize, SMEM_GEMM);
    cudaFuncSetAttribute(mmagemm<5>, cudaFuncAttributeMaxDynamicSharedMemorySize, SMEM_GEMM);
    cudaFuncSetAttribute(pv_kernel,  cudaFuncAttributeMaxDynamicSharedMemorySize, SMEM_PV);

    // prep: zero rowL, hs -> fp16, weight transpose, gates
    cudaMemsetAsync(rowL, 0, (size_t)Bv*NHv*Sv*sizeof(float));
    int n4 = M*Hv/4;
    cvt_kernel<<<(n4+255)/256, 256>>>(hs, hsh, n4);
    wsplit_kernel<<<dim3(24,24,4), 256>>>(Wq, Wk, Wv, Wo);
    gate_kernel<<<M/8, 128>>>(hs, Wg1, bg1, glnw, glnb, Wg2, bg2, gates);

    // fused QKV projection (1-term, N = 3H against stacked W^T)
    dim3 gQKV(3*Hv/128, M/128, 1);
    mmagemm<5><<<gQKV,256,SMEM_GEMM>>>(hsh,Hv,0, Wth,Hv,0,
        bq, bk, bvb, nullptr, nullptr,
        Qh, Kh, Vth, nullptr, nullptr, Hv);

    // scores (1-term, single k-iter) -> E = exp(gate*qk/8 + mask) fp16 + rowL
    dim3 gScore(Sv/128, Sv/128, Bv*NHv);
    mmagemm<3><<<gScore,256,SMEM_GEMM>>>(Qh,DHv,(size_t)Sv*DHv, Kh,DHv,(size_t)Sv*DHv,
        nullptr,nullptr,nullptr, gates, am,
        Eh, nullptr, nullptr, nullptr, rowL, DHv);

    // PV: probs = e*inv (fp32) + ctx = (E@V)*inv (fp16)
    pv_kernel<<<dim3(Sv/128, Bv*NHv), 256, SMEM_PV>>>(probs, Eh, Vth, rowL, ctxh);

    // out projection (1-term) + bias + residual, then LayerNorm
    dim3 gWo(Hv/128, M/128, 1);
    mmagemm<4><<<gWo,256,SMEM_GEMM>>>(ctxh,Hv,0, Wth+(size_t)3*Hv*Hv,Hv,0,
        bo, nullptr, nullptr, hs, nullptr,
        nullptr, nullptr, nullptr, preln, nullptr, Hv);
    ln_kernel<<<M,256>>>(preln, lnw, lnb, out);
}

// round 15
// speedup vs baseline: 1.1393x; 1.1393x over previous
#include <cuda_runtime.h>
#include <cuda_fp16.h>
#include <cstdint>

#define Bv 4
#define Sv 2048
#define Hv 768
#define NHv 12
#define DHv 64
#define WHv 128

typedef __half f16;
typedef unsigned int u32;

// ---------------- scratch (static device globals) ---------------------------
__device__ f16 g_hsh[(size_t)Bv*Sv*Hv];
__device__ f16 g_Wth[(size_t)4*Hv*Hv];      // W^T, rows: [q|k|v|o]
__device__ f16 g_Qh[(size_t)Bv*NHv*Sv*DHv];
__device__ f16 g_Kh[(size_t)Bv*NHv*Sv*DHv];
__device__ f16 g_Vth[(size_t)Bv*NHv*DHv*Sv];   // [z][dh][s]
__device__ f16 g_Eh[(size_t)Bv*NHv*Sv*Sv];     // unnormalized exp, fp16
__device__ f16 g_ctxh[(size_t)Bv*Sv*Hv];
__device__ float g_preln[(size_t)Bv*Sv*Hv];
__device__ float g_gates[Bv*NHv*Sv];
__device__ float g_rowL[Bv*NHv*Sv];

// ---------------- asm helpers ------------------------------------------------
__device__ __forceinline__ void mma16816(float& c0, float& c1, float& c2, float& c3,
                                         const u32 a[4], const u32 b[2]){
    asm volatile("mma.sync.aligned.m16n8k16.row.col.f32.f16.f16.f32 "
        "{%0,%1,%2,%3}, {%4,%5,%6,%7}, {%8,%9}, {%0,%1,%2,%3};"
        : "+f"(c0), "+f"(c1), "+f"(c2), "+f"(c3)
        : "r"(a[0]), "r"(a[1]), "r"(a[2]), "r"(a[3]), "r"(b[0]), "r"(b[1]));
}
__device__ __forceinline__ void cpa16(void* s, const void* g){
    asm volatile("cp.async.ca.shared.global [%0], [%1], 16;\n"
        :: "r"((u32)__cvta_generic_to_shared(s)), "l"(g));
}
__device__ __forceinline__ void ldm_x4(u32& r0,u32& r1,u32& r2,u32& r3, const void* p){
    asm volatile("ldmatrix.sync.aligned.m8n8.x4.shared.b16 {%0,%1,%2,%3}, [%4];"
        : "=r"(r0),"=r"(r1),"=r"(r2),"=r"(r3)
        : "r"((u32)__cvta_generic_to_shared(p)));
}
#define CP_COMMIT() asm volatile("cp.async.commit_group;\n")
#define CP_WAIT0()  asm volatile("cp.async.wait_group 0;\n")
#define CP_WAIT1()  asm volatile("cp.async.wait_group 1;\n")

// ---------------- prep kernels -----------------------------------------------
__global__ __launch_bounds__(256) void cvt_kernel(const float* __restrict__ x,
    f16* __restrict__ h, int n4)
{
    int i = blockIdx.x*256 + threadIdx.x;
    if (i >= n4) return;
    float4 v = ((const float4*)x)[i];
    ((__half2*)h)[i*2  ] = __floats2half2_rn(v.x, v.y);
    ((__half2*)h)[i*2+1] = __floats2half2_rn(v.z, v.w);
}

__global__ __launch_bounds__(256) void wsplit_kernel(
    const float* __restrict__ w0, const float* __restrict__ w1,
    const float* __restrict__ w2, const float* __restrict__ w3)
{
    __shared__ float t[32][33];
    const float* W = blockIdx.z==0 ? w0 : blockIdx.z==1 ? w1 : blockIdx.z==2 ? w2 : w3;
    f16* oh = g_Wth + (size_t)blockIdx.z*Hv*Hv;
    int k0 = blockIdx.y*32, n0 = blockIdx.x*32;
    int tx = threadIdx.x & 31, ty = threadIdx.x >> 5;   // (32,8)
    #pragma unroll
    for (int r=0;r<32;r+=8) t[ty+r][tx] = W[(size_t)(k0+ty+r)*Hv + n0+tx];
    __syncthreads();
    #pragma unroll
    for (int r=0;r<32;r+=8){
        float v = t[tx][ty+r];                 // = W[k0+tx][n0+ty+r]
        oh[(size_t)(n0+ty+r)*Hv + k0+tx] = __float2half_rn(v);
    }
}

// ---------------- 1-term fp16 GEMM, 3-stage cp.async, 1 barrier/iter ---------
// C[M,N] = A[M,K] @ B^T[N,K]
// MODE 3: scores -> E = exp(gate*qk/8 + mask) fp16 + rowL atomics
// MODE 4: Wo proj -> preln fp32, +bias +resid
// MODE 5: fused QKV (N=3H): Q,K -> fp16 [b,nh,s,dh]; V -> fp16 [b,nh,dh,s]
template<int MODE>
__global__ __launch_bounds__(256,2) void mmagemm(
    const f16* __restrict__ Ah, int lda, size_t sA,
    const f16* __restrict__ Bh, int ldb, size_t sB,
    const float* __restrict__ bias0, const float* __restrict__ bias1,
    const float* __restrict__ bias2,
    const float* __restrict__ e1,   // gates (M3) / resid (M4)
    const float* __restrict__ e2,   // attention_mask (M3)
    f16* __restrict__ O0, f16* __restrict__ O1, f16* __restrict__ O2,
    float* __restrict__ Of, float* __restrict__ Ex,
    int K)
{
    constexpr int LDSK = 40;
    constexpr int BUF  = 128*LDSK;
    extern __shared__ f16 smem[];
    f16* sAh = smem;                 // 3 stages
    f16* sBh = sAh + 3*BUF;          // 3 stages

    const int tid  = threadIdx.x, lane = tid & 31, warp = tid >> 5;
    const int grp  = lane >> 2,   tig  = lane & 3;
    const int z    = blockIdx.z;
    const int row0 = blockIdx.y*128, col0 = blockIdx.x*128;
    const f16* A_h = Ah + (size_t)z*sA;
    const f16* B_h = Bh + (size_t)z*sB;
    const int warpM = (warp>>2)*64, warpN = (warp&3)*32;
    const int lr = tid>>2, lcc = (tid&3)*8;
    const int aRow  = lane & 15,        aCol8 = (lane >> 4) * 8;
    const int bRow  = (lane & 7) + ((lane >> 4) << 3);
    const int bCol8 = ((lane >> 3) & 1) * 8;

    float c[4][4][4];
    #pragma unroll
    for (int i=0;i<4;i++)
        #pragma unroll
        for (int j=0;j<4;j++)
            #pragma unroll
            for (int r=0;r<4;r++) c[i][j][r]=0.f;

    auto load_tile = [&](int kt, int st){
        const int k0 = kt*32;
        f16* dAh = sAh + st*BUF; f16* dBh = sBh + st*BUF;
        #pragma unroll
        for (int t=0;t<2;t++){
            int r = lr + t*64;
            cpa16(&dAh[r*LDSK+lcc], &A_h[(size_t)(row0+r)*lda + k0+lcc]);
            cpa16(&dBh[r*LDSK+lcc], &B_h[(size_t)(col0+r)*ldb + k0+lcc]);
        }
    };

    const int KT = K/32;
    load_tile(0, 0); CP_COMMIT();
    if (KT > 1){ load_tile(1, 1); CP_COMMIT(); }

    for (int kt=0; kt<KT; kt++){
        if (kt+1 < KT) CP_WAIT1(); else CP_WAIT0();   // stage kt arrived
        __syncthreads();                               // visible + WAR for kt+2
        if (kt+2 < KT){ load_tile(kt+2, (kt+2)%3); CP_COMMIT(); }
        const int st = kt % 3;
        const f16* pAh = sAh + st*BUF;
        const f16* pBh = sBh + st*BUF;
        #pragma unroll
        for (int ks=0;ks<32;ks+=16){
            u32 a[4][4], b_h[4][2];
            #pragma unroll
            for (int jj=0; jj<4; jj+=2)
                ldm_x4(b_h[jj][0], b_h[jj][1], b_h[jj+1][0], b_h[jj+1][1],
                       &pBh[(warpN + jj*8 + bRow)*LDSK + ks + bCol8]);
            #pragma unroll
            for (int i=0;i<4;i++)
                ldm_x4(a[i][0],a[i][1],a[i][2],a[i][3],
                       &pAh[(warpM + i*16 + aRow)*LDSK + ks + aCol8]);
            #pragma unroll
            for (int i=0;i<4;i++)
                #pragma unroll
                for (int j=0;j<4;j++)
                    mma16816(c[i][j][0],c[i][j][1],c[i][j][2],c[i][j][3], a[i], b_h[j]);
        }
    }

    if (MODE==3){
        // E = exp(...) stored fp16 + rowL atomics (fp32 partial sums)
        float* rowLp = Ex + (size_t)z*Sv;
        const float* mk = e2 + (size_t)(z/NHv)*Sv;
        f16* Ez = O0 + (size_t)z*Sv*Sv;
        #pragma unroll
        for (int i=0;i<4;i++){
            #pragma unroll
            for (int half=0; half<2; half++){
                int r = row0 + warpM + i*16 + grp + half*8;
                float g = e1[(size_t)z*Sv + r]*0.125f;
                float rs = 0.f;
                #pragma unroll
                for (int j=0;j<4;j++){
                    int cn = col0 + warpN + j*8 + tig*2;
                    float s0 = c[i][j][half*2  ]*g + (1.f-mk[cn  ])*-10000.f;
                    float s1 = c[i][j][half*2+1]*g + (1.f-mk[cn+1])*-10000.f;
                    float e0 = __expf(s0), e1v = __expf(s1);
                    rs += e0 + e1v;
                    *(__half2*)(Ez + (size_t)r*Sv + cn) = __floats2half2_rn(e0, e1v);
                }
                rs += __shfl_xor_sync(0xffffffffu, rs, 1);
                rs += __shfl_xor_sync(0xffffffffu, rs, 2);
                if (tig==0) atomicAdd(&rowLp[r], rs);
            }
        }
    } else if (MODE==5){
        const int w = col0/Hv;                 // 0=Q 1=K 2=V
        const float* bias = w==0?bias0 : w==1?bias1 : bias2;
        #pragma unroll
        for (int i=0;i<4;i++){
            #pragma unroll
            for (int j=0;j<4;j++){
                int cn  = col0 + warpN + j*8 + tig*2;
                int cl  = cn - w*Hv;
                int nh  = cl>>6, dh = cl&63;
                #pragma unroll
                for (int half=0; half<2; half++){
                    int r = row0 + warpM + i*16 + grp + half*8;
                    float x0 = c[i][j][half*2  ] + bias[cl  ];
                    float x1 = c[i][j][half*2+1] + bias[cl+1];
                    int b=r/Sv, s=r-b*Sv;
                    if (w<2){
                        size_t idx = (((size_t)(b*NHv+nh)*Sv+s)<<6)+dh;
                        f16* PO = w==0 ? O0 : O1;
                        *(__half2*)(PO+idx) = __floats2half2_rn(x0,x1);
                    } else {
                        size_t i0 = ((size_t)(b*NHv+nh)*DHv+dh)*Sv + s;
                        O2[i0]    = __float2half_rn(x0);
                        O2[i0+Sv] = __float2half_rn(x1);
                    }
                }
            }
        }
    } else {   // MODE 4: Of = preln, e1 = residual (hs)
        #pragma unroll
        for (int i=0;i<4;i++){
            #pragma unroll
            for (int j=0;j<4;j++){
                int cn = col0 + warpN + j*8 + tig*2;
                #pragma unroll
                for (int half=0; half<2; half++){
                    int r = row0 + warpM + i*16 + grp + half*8;
                    size_t idx = (size_t)r*Hv + cn;
                    float2 o;
                    o.x = c[i][j][half*2  ] + bias0[cn  ] + e1[idx  ];
                    o.y = c[i][j][half*2+1] + bias0[cn+1] + e1[idx+1];
                    *(float2*)(Of+idx) = o;
                }
            }
        }
    }
}

// ---------------- PV: probs = e*inv (fp32) + ctx = (E@V)*inv, 3-stage --------
__global__ __launch_bounds__(256,2) void pv_kernel(
    float* __restrict__ probs,
    const f16* __restrict__ Eh, const f16* __restrict__ Vth,
    const float* __restrict__ rowL,
    f16* __restrict__ ctxh)
{
    constexpr int LDSK = 40;
    constexpr int EST  = 128*LDSK;             // f16 elems per E stage
    constexpr int VST  = 64*LDSK;              // f16 elems per V stage
    extern __shared__ char pvs[];
    f16* sE  = (f16*)pvs;                                   // 3 st * 10240B
    f16* sV  = (f16*)(pvs + 30720);                         // 3 st * 5120B
    float* sI = (float*)(pvs + 46080);                      // 512B

    const int tid = threadIdx.x, lane = tid & 31, warp = tid >> 5;
    const int grp = lane >> 2, tig = lane & 3;
    const int z = blockIdx.y, q0 = blockIdx.x*128;
    const int aRow  = lane & 15,        aCol8 = (lane >> 4) * 8;
    const int bRow  = (lane & 7) + ((lane >> 4) << 3);
    const int bCol8 = ((lane >> 3) & 1) * 8;

    if (tid < 128) sI[tid] = 1.f / rowL[(size_t)z*Sv + q0 + tid];

    const int warpM = (warp>>1)*32, warpN = (warp&1)*32;
    float c[2][4][4];
    #pragma unroll
    for (int i=0;i<2;i++)
        #pragma unroll
        for (int j=0;j<4;j++)
            #pragma unroll
            for (int r=0;r<4;r++) c[i][j][r]=0.f;

    float* Pz = probs + (size_t)z*Sv*Sv;
    const f16* Ez = Eh + (size_t)z*Sv*Sv;
    const f16* V_ = Vth + (size_t)z*DHv*Sv;

    auto prefetch = [&](int kt, int st){
        const int k0 = kt*32;
        #pragma unroll
        for (int t=0;t<2;t++){
            int ch = tid + t*256;              // 512 16B-chunks of E tile
            int r = ch>>2, q = (ch&3)*8;
            cpa16(&sE[st*EST + r*LDSK + q], &Ez[(size_t)(q0+r)*Sv + k0 + q]);
        }
        int r = tid>>2, cc = (tid&3)*8;
        cpa16(&sV[st*VST + r*LDSK+cc], &V_[(size_t)r*Sv + k0 + cc]);
    };

    const int KT = Sv/32;
    prefetch(0, 0); CP_COMMIT();
    prefetch(1, 1); CP_COMMIT();
    const int cr = tid>>1, cc0 = (tid&1)*16;   // probs-write mapping

    for (int kt=0; kt<KT; kt++){
        if (kt+1 < KT) CP_WAIT1(); else CP_WAIT0();
        __syncthreads();
        if (kt+2 < KT){ prefetch(kt+2, (kt+2)%3); CP_COMMIT(); }
        const int st = kt % 3;
        {   // probs = e*inv (fp32) straight from smem
            const int k0 = kt*32;
            const float inv = sI[cr];
            const f16* pe = sE + st*EST + cr*LDSK;
            #pragma unroll
            for (int c4=0;c4<4;c4++){
                int cc = cc0 + c4*4;
                __half2 e01 = *(__half2*)(pe+cc);
                __half2 e23 = *(__half2*)(pe+cc+2);
                float4 o;
                o.x = __low2float(e01)*inv;  o.y = __high2float(e01)*inv;
                o.z = __low2float(e23)*inv;  o.w = __high2float(e23)*inv;
                *(float4*)&Pz[(size_t)(q0+cr)*Sv + k0 + cc] = o;
            }
        }
        const f16* pE = sE + st*EST;
        const f16* pV = sV + st*VST;
        #pragma unroll
        for (int ks=0;ks<32;ks+=16){
            u32 a[2][4], b_h[4][2];
            #pragma unroll
            for (int jj=0; jj<4; jj+=2)
                ldm_x4(b_h[jj][0], b_h[jj][1], b_h[jj+1][0], b_h[jj+1][1],
                       &pV[(warpN + jj*8 + bRow)*LDSK + ks + bCol8]);
            #pragma unroll
            for (int i=0;i<2;i++)
                ldm_x4(a[i][0],a[i][1],a[i][2],a[i][3],
                       &pE[(warpM + i*16 + aRow)*LDSK + ks + aCol8]);
            #pragma unroll
            for (int i=0;i<2;i++)
                #pragma unroll
                for (int j=0;j<4;j++)
                    mma16816(c[i][j][0],c[i][j][1],c[i][j][2],c[i][j][3], a[i], b_h[j]);
        }
    }

    const int b = z/NHv, nh = z%NHv;
    #pragma unroll
    for (int i=0;i<2;i++){
        #pragma unroll
        for (int j=0;j<4;j++){
            int dh = warpN + j*8 + tig*2;
            #pragma unroll
            for (int half=0; half<2; half++){
                int sl = warpM + i*16 + grp + half*8;
                int s  = q0 + sl;
                float inv = sI[sl];
                float x0 = c[i][j][half*2]*inv, x1 = c[i][j][half*2+1]*inv;
                size_t idx = ((size_t)b*Sv + s)*Hv + nh*DHv + dh;
                *(__half2*)(ctxh+idx) = __floats2half2_rn(x0,x1);
            }
        }
    }
}

// ---------------- helpers ----------------------------------------------------
__device__ __forceinline__ float blockReduceSum(float v, float* red){
    #pragma unroll
    for (int o=16;o;o>>=1) v += __shfl_xor_sync(0xffffffffu, v, o);
    const int lane = threadIdx.x & 31, wid = threadIdx.x >> 5;
    const int nw = blockDim.x >> 5;
    __syncthreads();
    if (lane==0) red[wid]=v;
    __syncthreads();
    if (threadIdx.x==0){
        float s=0.f;
        for (int i=0;i<nw;i++) s+=red[i];
        red[32]=s;
    }
    __syncthreads();
    return red[32];
}

// ---------------- wormhole gate ----------------------------------------------
__global__ __launch_bounds__(128) void gate_kernel(
    const float* __restrict__ hs, const float* __restrict__ Wg1, const float* __restrict__ bg1,
    const float* __restrict__ glnw, const float* __restrict__ glnb,
    const float* __restrict__ Wg2, const float* __restrict__ bg2,
    float* __restrict__ gates)
{
    const int ROWS=8;
    __shared__ float hs_s[ROWS*Hv];
    __shared__ float g_s[ROWS][WHv+4];
    __shared__ float red[40];
    const int tid = threadIdx.x;
    const size_t rowbase = (size_t)blockIdx.x*ROWS;

    for (int i=tid;i<ROWS*Hv;i+=128) hs_s[i] = hs[rowbase*Hv + i];
    __syncthreads();

    float acc[ROWS];
    #pragma unroll
    for (int r=0;r<ROWS;r++) acc[r]=bg1[tid];
    for (int h=0;h<Hv;h++){
        float wv = Wg1[h*WHv + tid];
        #pragma unroll
        for (int r=0;r<ROWS;r++) acc[r] = fmaf(hs_s[r*Hv+h], wv, acc[r]);
    }
    float lw = glnw[tid], lb = glnb[tid];
    #pragma unroll
    for (int r=0;r<ROWS;r++){
        float mu  = blockReduceSum(acc[r], red) * (1.f/WHv);
        float d   = acc[r]-mu;
        float var = blockReduceSum(d*d, red) * (1.f/WHv);
        float gv  = d*rsqrtf(var+1e-12f)*lw + lb;
        g_s[r][tid] = fmaxf(gv, 0.f);
    }
    __syncthreads();
    if (tid < ROWS*NHv){
        int r = tid/NHv, o = tid%NHv;
        float s = bg2[o];
        for (int c=0;c<WHv;c++) s = fmaf(g_s[r][c], Wg2[c*NHv+o], s);
        float gate = 1.f/(1.f+__expf(-s));
        size_t row = rowbase + r;
        int b = (int)(row/Sv), sq = (int)(row%Sv);
        gates[((size_t)(b*NHv+o))*Sv + sq] = gate;
    }
}

// ---------------- final residual LayerNorm -----------------------------------
__global__ __launch_bounds__(256) void ln_kernel(const float* __restrict__ x,
    const float* __restrict__ w, const float* __restrict__ b, float* __restrict__ out)
{
    __shared__ float xs[Hv];
    __shared__ float red[40];
    const size_t row = blockIdx.x;
    const float* xr = x + row*Hv;
    float partial = 0.f;
    for (int i=threadIdx.x;i<Hv;i+=256){ float v=xr[i]; xs[i]=v; partial+=v; }
    float mu = blockReduceSum(partial, red)*(1.f/Hv);
    float p2=0.f;
    for (int i=threadIdx.x;i<Hv;i+=256){ float d=xs[i]-mu; p2+=d*d; }
    float var = blockReduceSum(p2, red)*(1.f/Hv);
    float rs = rsqrtf(var+1e-12f);
    float* o = out + row*Hv;
    for (int i=threadIdx.x;i<Hv;i+=256) o[i] = (xs[i]-mu)*rs*w[i] + b[i];
}

// ---------------- launcher ----------------------------------------------------
extern "C" void kernel_launch(void* const* d_in, const int* in_sizes, int n_in,
                              void* d_out, int out_size)
{
    const float* hs  =(const float*)d_in[0];
    const float* am  =(const float*)d_in[1];
    const float* Wq  =(const float*)d_in[2];
    const float* bq  =(const float*)d_in[3];
    const float* Wk  =(const float*)d_in[4];
    const float* bk  =(const float*)d_in[5];
    const float* Wv  =(const float*)d_in[6];
    const float* bvb =(const float*)d_in[7];
    const float* Wg1 =(const float*)d_in[8];
    const float* bg1 =(const float*)d_in[9];
    const float* glnw=(const float*)d_in[10];
    const float* glnb=(const float*)d_in[11];
    const float* Wg2 =(const float*)d_in[12];
    const float* bg2 =(const float*)d_in[13];
    const float* Wo  =(const float*)d_in[14];
    const float* bo  =(const float*)d_in[15];
    const float* lnw =(const float*)d_in[16];
    const float* lnb =(const float*)d_in[17];

    float* out   = (float*)d_out;
    float* probs = out + (size_t)Bv*Sv*Hv;   // tuple order: (out, probs)

    f16 *hsh,*Wth,*Qh,*Kh,*Vth,*Eh,*ctxh;
    float *preln,*gates,*rowL;
    cudaGetSymbolAddress((void**)&hsh,  g_hsh);
    cudaGetSymbolAddress((void**)&Wth,  g_Wth);
    cudaGetSymbolAddress((void**)&Qh,   g_Qh);
    cudaGetSymbolAddress((void**)&Kh,   g_Kh);
    cudaGetSymbolAddress((void**)&Vth,  g_Vth);
    cudaGetSymbolAddress((void**)&Eh,   g_Eh);
    cudaGetSymbolAddress((void**)&ctxh, g_ctxh);
    cudaGetSymbolAddress((void**)&preln,g_preln);
    cudaGetSymbolAddress((void**)&gates,g_gates);
    cudaGetSymbolAddress((void**)&rowL, g_rowL);

    const int M = Bv*Sv;
    const int SMEM_GEMM = 3*2*128*40*(int)sizeof(f16);   // 61440 B (3 stages)
    const int SMEM_PV   = 46592;

    cudaFuncSetAttribute(mmagemm<3>, cudaFuncAttributeMaxDynamicSharedMemorySize, SMEM_GEMM);
    cudaFuncSetAttribute(mmagemm<4>, cudaFuncAttributeMaxDynamicSharedMemorySize, SMEM_GEMM);
    cudaFuncSetAttribute(mmagemm<5>, cudaFuncAttributeMaxDynamicSharedMemorySize, SMEM_GEMM);
    cudaFuncSetAttribute(pv_kernel,  cudaFuncAttributeMaxDynamicSharedMemorySize, SMEM_PV);

    // prep: zero rowL, hs -> fp16, weight transpose, gates
    cudaMemsetAsync(rowL, 0, (size_t)Bv*NHv*Sv*sizeof(float));
    int n4 = M*Hv/4;
    cvt_kernel<<<(n4+255)/256, 256>>>(hs, hsh, n4);
    wsplit_kernel<<<dim3(24,24,4), 256>>>(Wq, Wk, Wv, Wo);
    gate_kernel<<<M/8, 128>>>(hs, Wg1, bg1, glnw, glnb, Wg2, bg2, gates);

    // fused QKV projection (1-term, N = 3H against stacked W^T)
    dim3 gQKV(3*Hv/128, M/128, 1);
    mmagemm<5><<<gQKV,256,SMEM_GEMM>>>(hsh,Hv,0, Wth,Hv,0,
        bq, bk, bvb, nullptr, nullptr,
        Qh, Kh, Vth, nullptr, nullptr, Hv);

    // scores (1-term) -> E = exp(gate*qk/8 + mask) fp16 + rowL sums
    dim3 gScore(Sv/128, Sv/128, Bv*NHv);
    mmagemm<3><<<gScore,256,SMEM_GEMM>>>(Qh,DHv,(size_t)Sv*DHv, Kh,DHv,(size_t)Sv*DHv,
        nullptr,nullptr,nullptr, gates, am,
        Eh, nullptr, nullptr, nullptr, rowL, DHv);

    // PV: probs = e*inv (fp32) + ctx = (E@V)*inv (fp16)
    pv_kernel<<<dim3(Sv/128, Bv*NHv), 256, SMEM_PV>>>(probs, Eh, Vth, rowL, ctxh);

    // out projection (1-term) + bias + residual, then LayerNorm
    dim3 gWo(Hv/128, M/128, 1);
    mmagemm<4><<<gWo,256,SMEM_GEMM>>>(ctxh,Hv,0, Wth+(size_t)3*Hv*Hv,Hv,0,
        bo, nullptr, nullptr, hs, nullptr,
        nullptr, nullptr, nullptr, preln, nullptr, Hv);
    ln_kernel<<<M,256>>>(preln, lnw, lnb, out);
}